// round 4
// baseline (speedup 1.0000x reference)
#include <cuda_runtime.h>
#include <math.h>
#include <stdint.h>

// ---------------------------------------------------------------------------
// Round 4: GEMM overhaul — transposed (N-major) weights so both operands use
// conflict-free ldmatrix, + 4-stage cp.async pipeline. Attention unchanged.
// ---------------------------------------------------------------------------

#define B_   2
#define N_   8192
#define D_   1024
#define H_   16
#define DH_  64
#define SEG_ 512
#define P_   16
#define NW_  16
#define ROWS_ (B_ * N_)      // 16384
#define EPS_ 1.1920929e-07f

__device__ float g_xn [(size_t)ROWS_ * D_];
__device__ float g_qkv[(size_t)ROWS_ * 3 * D_];
__device__ float g_q  [(size_t)32 * H_ * SEG_ * DH_];
__device__ float g_k  [(size_t)32 * H_ * SEG_ * DH_];
__device__ float g_v  [(size_t)32 * H_ * SEG_ * DH_];
__device__ float g_ao [(size_t)ROWS_ * D_];
__device__ float g_wq [(size_t)D_ * 3 * D_];   // Wqkv^T [3072][1024], tf32
__device__ float g_wo [(size_t)D_ * D_];       // Wout^T [1024][1024], tf32
__device__ float g_invf[32];

__device__ __forceinline__ float tf32r(float x) {
    uint32_t u;
    asm("cvt.rna.tf32.f32 %0, %1;" : "=r"(u) : "f"(x));
    return __uint_as_float(u);
}

__device__ __forceinline__ void mma_tf32(float* c, const uint32_t* a, const uint32_t* b) {
    asm volatile(
        "mma.sync.aligned.m16n8k8.row.col.f32.tf32.tf32.f32 "
        "{%0,%1,%2,%3}, {%4,%5,%6,%7}, {%8,%9}, {%0,%1,%2,%3};"
        : "+f"(c[0]), "+f"(c[1]), "+f"(c[2]), "+f"(c[3])
        : "r"(a[0]), "r"(a[1]), "r"(a[2]), "r"(a[3]), "r"(b[0]), "r"(b[1]));
}

__device__ __forceinline__ void ldm_x4(uint32_t* r, const float* p) {
    uint32_t saddr = (uint32_t)__cvta_generic_to_shared(p);
    asm volatile(
        "ldmatrix.sync.aligned.m8n8.x4.shared.b16 {%0,%1,%2,%3}, [%4];"
        : "=r"(r[0]), "=r"(r[1]), "=r"(r[2]), "=r"(r[3]) : "r"(saddr));
}

__device__ __forceinline__ void cp16(float* smem_dst, const float* gsrc) {
    uint32_t d = (uint32_t)__cvta_generic_to_shared(smem_dst);
    asm volatile("cp.async.cg.shared.global [%0], [%1], 16;" :: "r"(d), "l"(gsrc));
}
#define CP_COMMIT() asm volatile("cp.async.commit_group;")
#define CP_WAIT(n)  asm volatile("cp.async.wait_group %0;" :: "n"(n))

// ---------------------------------------------------------------------------
__global__ void precompute_kernel() {
    int t = threadIdx.x;
    if (t < 32)
        g_invf[t] = (float)(1.0 / pow(10000.0, (double)t / 32.0));
}

// W [K][Nw] row-major -> Wt [Nw][K] row-major with tf32 rounding.
__global__ void transpose_tf32_kernel(const float* __restrict__ src,
                                      float* __restrict__ dst, int K, int Nw) {
    __shared__ float t[32][33];
    int n0 = blockIdx.x * 32, k0 = blockIdx.y * 32;
    int x = threadIdx.x, y = threadIdx.y;      // 32 x 8
    #pragma unroll
    for (int i = 0; i < 32; i += 8)
        t[y + i][x] = src[(size_t)(k0 + y + i) * Nw + n0 + x];
    __syncthreads();
    #pragma unroll
    for (int i = 0; i < 32; i += 8)
        dst[(size_t)(n0 + y + i) * K + k0 + x] = tf32r(t[x][y + i]);
}

// ---------------------------------------------------------------------------
__global__ void rmsnorm_kernel(const float* __restrict__ seq,
                               const float* __restrict__ wn) {
    int row = blockIdx.x;
    int t = threadIdx.x;
    const float4* in = reinterpret_cast<const float4*>(seq + (size_t)row * D_);
    float4 x = in[t];
    float ss = x.x * x.x + x.y * x.y + x.z * x.z + x.w * x.w;
    #pragma unroll
    for (int o = 16; o; o >>= 1) ss += __shfl_xor_sync(0xffffffffu, ss, o);
    __shared__ float red[8];
    if ((t & 31) == 0) red[t >> 5] = ss;
    __syncthreads();
    float tot = 0.f;
    #pragma unroll
    for (int iw = 0; iw < 8; iw++) tot += red[iw];
    float r = rsqrtf(tot * (1.0f / 1024.0f) + EPS_);
    float4 wv = reinterpret_cast<const float4*>(wn)[t];
    float4 o;
    o.x = tf32r(x.x * r * wv.x);
    o.y = tf32r(x.y * r * wv.y);
    o.z = tf32r(x.z * r * wv.z);
    o.w = tf32r(x.w * r * wv.w);
    reinterpret_cast<float4*>(g_xn + (size_t)row * D_)[t] = o;
}

// ---------------------------------------------------------------------------
// TF32 GEMM: C[M,N] = A[M,K] @ Bt[N,K]^T. Both operands K-major in gmem.
// 128x128x16 tiles, 4-stage cp.async, 256 threads, warp tile 32x64.
// smem per stage: A[128][20] + B[128][20] = 5120 floats.
#define GLD   20
#define STG_  4
#define SSZ_  (2 * 128 * GLD)

__device__ __forceinline__ void gemm_stage_load(
    const float* __restrict__ Ab, const float* __restrict__ Btb, int K,
    float* __restrict__ sA, float* __restrict__ sB, int k0, int tid)
{
    #pragma unroll
    for (int i = 0; i < 2; i++) {
        int v = tid + i * 256;
        int r = v >> 2, kc = (v & 3) * 4;
        cp16(sA + r * GLD + kc, Ab + (size_t)r * K + k0 + kc);
        cp16(sB + r * GLD + kc, Btb + (size_t)r * K + k0 + kc);
    }
}

__global__ __launch_bounds__(256, 2)
void tf32_gemm_kernel(const float* __restrict__ A, const float* __restrict__ Bt,
                      float* __restrict__ C, int M, int N, int K) {
    extern __shared__ float smem[];

    int tid  = threadIdx.x;
    int warp = tid >> 5;
    int lane = tid & 31;
    int wm = warp >> 1;          // 0..3
    int wn = warp & 1;           // 0..1
    int g   = lane >> 2;
    int tig = lane & 3;
    int lrow = lane & 15;
    int lseg = (lane >> 4) * 4;

    const float* Ab  = A  + (size_t)blockIdx.y * 128 * K;
    const float* Btb = Bt + (size_t)blockIdx.x * 128 * K;

    float acc[2][8][4];
    #pragma unroll
    for (int a = 0; a < 2; a++)
        #pragma unroll
        for (int b = 0; b < 8; b++)
            #pragma unroll
            for (int c = 0; c < 4; c++) acc[a][b][c] = 0.f;

    int NK = K >> 4;

    #pragma unroll
    for (int s = 0; s < STG_ - 1; s++) {
        gemm_stage_load(Ab, Btb, K, smem + s * SSZ_, smem + s * SSZ_ + 128 * GLD,
                        s * 16, tid);
        CP_COMMIT();
    }

    for (int kt = 0; kt < NK; kt++) {
        CP_WAIT(STG_ - 2);
        __syncthreads();

        int kn = kt + STG_ - 1;
        if (kn < NK) {
            int buf = kn & (STG_ - 1);
            gemm_stage_load(Ab, Btb, K, smem + buf * SSZ_,
                            smem + buf * SSZ_ + 128 * GLD, kn * 16, tid);
        }
        CP_COMMIT();

        const float* sA = smem + (kt & (STG_ - 1)) * SSZ_;
        const float* sB = sA + 128 * GLD;

        #pragma unroll
        for (int ks = 0; ks < 2; ks++) {
            uint32_t afr[2][4];
            #pragma unroll
            for (int tm = 0; tm < 2; tm++)
                ldm_x4(afr[tm], sA + (wm * 32 + tm * 16 + lrow) * GLD + ks * 8 + lseg);
            uint32_t bfr[4][4];
            #pragma unroll
            for (int bj = 0; bj < 4; bj++)
                ldm_x4(bfr[bj], sB + (wn * 64 + bj * 16 + lrow) * GLD + ks * 8 + lseg);
            // bfr[bj] = { b0(j=2bj), b0(j=2bj+1), b1(j=2bj), b1(j=2bj+1) }
            #pragma unroll
            for (int tm = 0; tm < 2; tm++)
                #pragma unroll
                for (int j = 0; j < 8; j++) {
                    uint32_t b[2] = { bfr[j >> 1][j & 1], bfr[j >> 1][2 + (j & 1)] };
                    mma_tf32(acc[tm][j], afr[tm], b);
                }
        }
    }

    int rbase = blockIdx.y * 128 + wm * 32;
    int cbase = blockIdx.x * 128 + wn * 64;
    #pragma unroll
    for (int tm = 0; tm < 2; tm++) {
        #pragma unroll
        for (int j = 0; j < 8; j++) {
            int row0 = rbase + tm * 16 + g;
            int col  = cbase + j * 8 + 2 * tig;
            *reinterpret_cast<float2*>(&C[(size_t)row0 * N + col]) =
                make_float2(acc[tm][j][0], acc[tm][j][1]);
            *reinterpret_cast<float2*>(&C[(size_t)(row0 + 8) * N + col]) =
                make_float2(acc[tm][j][2], acc[tm][j][3]);
        }
    }
}

// ---------------------------------------------------------------------------
__global__ void rope_split_kernel() {
    int idx = blockIdx.x * blockDim.x + threadIdx.x;
    if (idx >= ROWS_ * H_ * 32) return;
    int t   = idx & 31;
    int h   = (idx >> 5) & 15;
    int row = idx >> 9;
    int n   = row & (N_ - 1);
    int b   = row >> 13;
    int w   = n >> 9;
    int s   = n & (SEG_ - 1);
    int seg = b * NW_ + w;

    const float* base = g_qkv + (size_t)row * 3072 + h * 64 + 2 * t;
    float q0 = base[0],    q1 = base[1];
    float k0 = base[1024], k1 = base[1025];
    float v0 = base[2048], v1 = base[2049];

    float ang = (float)n * g_invf[t];
    double ad = (double)ang;
    double kq = trunc(ad * 0.15915494309189535);
    ad -= kq * 6.283185307179586;
    float sn, cs;
    sincosf((float)ad, &sn, &cs);

    float qo0 = q0 * cs - q1 * sn;
    float qo1 = q1 * cs + q0 * sn;
    float ko0 = k0 * cs - k1 * sn;
    float ko1 = k1 * cs + k0 * sn;

    size_t dst = (((size_t)seg * H_ + h) * SEG_ + s) * DH_ + 2 * t;
    const float SC = 0.125f;
    g_q[dst] = tf32r(qo0 * SC); g_q[dst + 1] = tf32r(qo1 * SC);
    g_k[dst] = tf32r(ko0);      g_k[dst + 1] = tf32r(ko1);
    g_v[dst] = tf32r(v0);       g_v[dst + 1] = tf32r(v1);
}

// ---------------------------------------------------------------------------
// Tensor-core flash attention (unchanged from round 3).
#define KP_ 72
#define PP_ 40

template<int NJ, bool PM>
__device__ __forceinline__ void attn_step(
    const float (*S)[KP_], float (*Psw)[PP_],
    const uint32_t qf[8][4], float o[8][4],
    float& m0, float& m1, float& l0, float& l1,
    int kv0, int i0, int i1, int g, int tig)
{
    float s[NJ][4];
    #pragma unroll
    for (int j = 0; j < NJ; j++)
        s[j][0] = s[j][1] = s[j][2] = s[j][3] = 0.f;

    #pragma unroll
    for (int ks = 0; ks < 8; ks++) {
        uint32_t b[NJ][2];
        #pragma unroll
        for (int j = 0; j < NJ; j++) {
            b[j][0] = __float_as_uint(S[j * 8 + g][ks * 8 + tig]);
            b[j][1] = __float_as_uint(S[j * 8 + g][ks * 8 + tig + 4]);
        }
        #pragma unroll
        for (int j = 0; j < NJ; j++)
            mma_tf32(s[j], qf[ks], b[j]);
    }

    if (!PM) {
        #pragma unroll
        for (int j = 0; j < NJ; j++) {
            int c0 = kv0 + j * 8 + 2 * tig;
            if (c0     > i0) s[j][0] = -1e30f;
            if (c0 + 1 > i0) s[j][1] = -1e30f;
            if (c0     > i1) s[j][2] = -1e30f;
            if (c0 + 1 > i1) s[j][3] = -1e30f;
        }
    }

    float cm0 = -1e30f, cm1 = -1e30f;
    #pragma unroll
    for (int j = 0; j < NJ; j++) {
        cm0 = fmaxf(cm0, fmaxf(s[j][0], s[j][1]));
        cm1 = fmaxf(cm1, fmaxf(s[j][2], s[j][3]));
    }
    cm0 = fmaxf(cm0, __shfl_xor_sync(0xffffffffu, cm0, 1));
    cm0 = fmaxf(cm0, __shfl_xor_sync(0xffffffffu, cm0, 2));
    cm1 = fmaxf(cm1, __shfl_xor_sync(0xffffffffu, cm1, 1));
    cm1 = fmaxf(cm1, __shfl_xor_sync(0xffffffffu, cm1, 2));

    float m0n = fmaxf(m0, cm0), m1n = fmaxf(m1, cm1);
    float cr0 = __expf(m0 - m0n), cr1 = __expf(m1 - m1n);
    m0 = m0n; m1 = m1n;

    float ps0 = 0.f, ps1 = 0.f;
    #pragma unroll
    for (int j = 0; j < NJ; j++) {
        float p0 = __expf(s[j][0] - m0n);
        float p1 = __expf(s[j][1] - m0n);
        float p2 = __expf(s[j][2] - m1n);
        float p3 = __expf(s[j][3] - m1n);
        ps0 += p0 + p1;
        ps1 += p2 + p3;
        *reinterpret_cast<float2*>(&Psw[g][j * 8 + 2 * tig])     = make_float2(p0, p1);
        *reinterpret_cast<float2*>(&Psw[g + 8][j * 8 + 2 * tig]) = make_float2(p2, p3);
    }
    ps0 += __shfl_xor_sync(0xffffffffu, ps0, 1);
    ps0 += __shfl_xor_sync(0xffffffffu, ps0, 2);
    ps1 += __shfl_xor_sync(0xffffffffu, ps1, 1);
    ps1 += __shfl_xor_sync(0xffffffffu, ps1, 2);
    l0 = l0 * cr0 + ps0;
    l1 = l1 * cr1 + ps1;

    #pragma unroll
    for (int j = 0; j < 8; j++) {
        o[j][0] *= cr0; o[j][1] *= cr0;
        o[j][2] *= cr1; o[j][3] *= cr1;
    }

    __syncwarp();
    #pragma unroll
    for (int ks2 = 0; ks2 < NJ; ks2++) {
        uint32_t a[4];
        a[0] = __float_as_uint(Psw[g][ks2 * 8 + tig]);
        a[1] = __float_as_uint(Psw[g + 8][ks2 * 8 + tig]);
        a[2] = __float_as_uint(Psw[g][ks2 * 8 + tig + 4]);
        a[3] = __float_as_uint(Psw[g + 8][ks2 * 8 + tig + 4]);
        #pragma unroll
        for (int j = 0; j < 8; j++) {
            uint32_t b[2];
            b[0] = __float_as_uint(S[32 + ks2 * 8 + tig][j * 8 + g]);
            b[1] = __float_as_uint(S[32 + ks2 * 8 + tig + 4][j * 8 + g]);
            mma_tf32(o[j], a, b);
        }
    }
}

__global__ __launch_bounds__(128)
void attn_mma_kernel(const float* __restrict__ pm) {
    int qt  = blockIdx.x;
    int h   = blockIdx.y;
    int seg = blockIdx.z;
    int tid = threadIdx.x;
    int w    = tid >> 5;
    int lane = tid & 31;
    int g   = lane >> 2;
    int tig = lane & 3;

    __shared__ float S[64][KP_];
    __shared__ float Ps[4][16][PP_];

    const float* qbase = g_q + (((size_t)seg * H_ + h) * SEG_ + qt * 64) * DH_;
    #pragma unroll
    for (int i = 0; i < 8; i++) {
        int idx = tid + i * 128;
        int r = idx >> 4, c = idx & 15;
        *reinterpret_cast<float4*>(&S[r][c * 4]) =
            *reinterpret_cast<const float4*>(qbase + (size_t)r * DH_ + c * 4);
    }
    __syncthreads();

    uint32_t qf[8][4];
    #pragma unroll
    for (int ks = 0; ks < 8; ks++) {
        qf[ks][0] = __float_as_uint(S[w * 16 + g][ks * 8 + tig]);
        qf[ks][1] = __float_as_uint(S[w * 16 + g + 8][ks * 8 + tig]);
        qf[ks][2] = __float_as_uint(S[w * 16 + g][ks * 8 + tig + 4]);
        qf[ks][3] = __float_as_uint(S[w * 16 + g + 8][ks * 8 + tig + 4]);
    }

    float o[8][4];
    #pragma unroll
    for (int j = 0; j < 8; j++)
        o[j][0] = o[j][1] = o[j][2] = o[j][3] = 0.f;
    float m0 = -1e30f, m1 = -1e30f, l0 = 0.f, l1 = 0.f;

    int i0 = qt * 64 + w * 16 + g;
    int i1 = i0 + 8;

    const float* kb  = g_k + (((size_t)seg * H_ + h) * SEG_) * DH_;
    const float* vb  = g_v + (((size_t)seg * H_ + h) * SEG_) * DH_;
    const float* pmk = pm + (size_t)h * P_ * DH_;
    const float* pmv = pm + (size_t)(H_ + h) * P_ * DH_;

    int nseg = 2 * qt + 2;

    for (int ch = 0; ch <= nseg; ch++) {
        __syncthreads();
        if (ch == 0) {
            #pragma unroll
            for (int i = 0; i < 2; i++) {
                int idx = tid + i * 128;
                int r = idx >> 4, c = idx & 15;
                *reinterpret_cast<float4*>(&S[r][c * 4]) =
                    *reinterpret_cast<const float4*>(pmk + (size_t)r * DH_ + c * 4);
                *reinterpret_cast<float4*>(&S[32 + r][c * 4]) =
                    *reinterpret_cast<const float4*>(pmv + (size_t)r * DH_ + c * 4);
            }
        } else {
            int kv0 = (ch - 1) * 32;
            #pragma unroll
            for (int i = 0; i < 4; i++) {
                int idx = tid + i * 128;
                int r = idx >> 4, c = idx & 15;
                *reinterpret_cast<float4*>(&S[r][c * 4]) =
                    *reinterpret_cast<const float4*>(kb + (size_t)(kv0 + r) * DH_ + c * 4);
                *reinterpret_cast<float4*>(&S[32 + r][c * 4]) =
                    *reinterpret_cast<const float4*>(vb + (size_t)(kv0 + r) * DH_ + c * 4);
            }
        }
        __syncthreads();

        if (ch == 0)
            attn_step<2, true>(S, Ps[w], qf, o, m0, m1, l0, l1, 0, i0, i1, g, tig);
        else
            attn_step<4, false>(S, Ps[w], qf, o, m0, m1, l0, l1, (ch - 1) * 32, i0, i1, g, tig);
    }

    float inv0 = 1.f / l0, inv1 = 1.f / l1;
    size_t r0 = (size_t)(seg * SEG_ + i0) * D_ + h * DH_;
    size_t r1 = (size_t)(seg * SEG_ + i1) * D_ + h * DH_;
    #pragma unroll
    for (int j = 0; j < 8; j++) {
        int col = j * 8 + 2 * tig;
        *reinterpret_cast<float2*>(&g_ao[r0 + col]) =
            make_float2(tf32r(o[j][0] * inv0), tf32r(o[j][1] * inv0));
        *reinterpret_cast<float2*>(&g_ao[r1 + col]) =
            make_float2(tf32r(o[j][2] * inv1), tf32r(o[j][3] * inv1));
    }
}

// ---------------------------------------------------------------------------
extern "C" void kernel_launch(void* const* d_in, const int* in_sizes, int n_in,
                              void* d_out, int out_size) {
    const float* seq    = (const float*)d_in[0];
    const float* w_norm = (const float*)d_in[1];
    const float* Wqkv   = (const float*)d_in[2];
    const float* Wout   = (const float*)d_in[3];
    const float* pm     = (const float*)d_in[4];
    float* out = (float*)d_out;

    float* xn  = nullptr; cudaGetSymbolAddress((void**)&xn,  g_xn);
    float* qkv = nullptr; cudaGetSymbolAddress((void**)&qkv, g_qkv);
    float* ao  = nullptr; cudaGetSymbolAddress((void**)&ao,  g_ao);
    float* wq  = nullptr; cudaGetSymbolAddress((void**)&wq,  g_wq);
    float* wo  = nullptr; cudaGetSymbolAddress((void**)&wo,  g_wo);

    const int gemm_smem = STG_ * SSZ_ * 4;   // 81920 B
    cudaFuncSetAttribute(tf32_gemm_kernel,
                         cudaFuncAttributeMaxDynamicSharedMemorySize, gemm_smem);

    precompute_kernel<<<1, 32>>>();
    {
        dim3 blk(32, 8);
        dim3 grq(3072 / 32, 1024 / 32);
        transpose_tf32_kernel<<<grq, blk>>>(Wqkv, wq, 1024, 3072);
        dim3 gro(1024 / 32, 1024 / 32);
        transpose_tf32_kernel<<<gro, blk>>>(Wout, wo, 1024, 1024);
    }
    rmsnorm_kernel<<<ROWS_, 256>>>(seq, w_norm);
    {
        dim3 grid(3072 / 128, ROWS_ / 128);
        tf32_gemm_kernel<<<grid, 256, gemm_smem>>>(xn, wq, qkv, ROWS_, 3072, 1024);
    }
    {
        int total = ROWS_ * H_ * 32;
        rope_split_kernel<<<(total + 255) / 256, 256>>>();
    }
    {
        dim3 grid(8, H_, 32);
        attn_mma_kernel<<<grid, 128>>>(pm);
    }
    {
        dim3 grid(1024 / 128, ROWS_ / 128);
        tf32_gemm_kernel<<<grid, 256, gemm_smem>>>(ao, wo, out, ROWS_, 1024, 1024);
    }
}

// round 7
// speedup vs baseline: 1.2142x; 1.2142x over previous
#include <cuda_runtime.h>
#include <cuda_fp16.h>
#include <math.h>
#include <stdint.h>

// ---------------------------------------------------------------------------
// Round 7: fp16 mma.sync.m16n8k16 GEMMs (tcgen05 unavailable: harness PTX
// targets sm_103 without the 'a' feature). Attention stays tf32 mma.
// ---------------------------------------------------------------------------

#define B_   2
#define N_   8192
#define D_   1024
#define H_   16
#define DH_  64
#define SEG_ 512
#define P_   16
#define NW_  16
#define ROWS_ (B_ * N_)      // 16384
#define EPS_ 1.1920929e-07f

__device__ __half g_xnh [(size_t)ROWS_ * D_];        // rmsnorm out, fp16
__device__ float  g_qkv [(size_t)ROWS_ * 3 * D_];
__device__ float  g_q   [(size_t)32 * H_ * SEG_ * DH_];
__device__ float  g_k   [(size_t)32 * H_ * SEG_ * DH_];
__device__ float  g_v   [(size_t)32 * H_ * SEG_ * DH_];
__device__ __half g_aoh [(size_t)ROWS_ * D_];        // attention out, fp16
__device__ __half g_wqh [(size_t)D_ * 3 * D_];       // Wqkv^T [3072][1024] fp16
__device__ __half g_woh [(size_t)D_ * D_];           // Wout^T [1024][1024] fp16
__device__ float  g_invf[32];

__device__ __forceinline__ float tf32r(float x) {
    uint32_t u;
    asm("cvt.rna.tf32.f32 %0, %1;" : "=r"(u) : "f"(x));
    return __uint_as_float(u);
}

__device__ __forceinline__ void mma_tf32(float* c, const uint32_t* a, const uint32_t* b) {
    asm volatile(
        "mma.sync.aligned.m16n8k8.row.col.f32.tf32.tf32.f32 "
        "{%0,%1,%2,%3}, {%4,%5,%6,%7}, {%8,%9}, {%0,%1,%2,%3};"
        : "+f"(c[0]), "+f"(c[1]), "+f"(c[2]), "+f"(c[3])
        : "r"(a[0]), "r"(a[1]), "r"(a[2]), "r"(a[3]), "r"(b[0]), "r"(b[1]));
}

__device__ __forceinline__ void mma_f16(float* c, const uint32_t* a, const uint32_t* b) {
    asm volatile(
        "mma.sync.aligned.m16n8k16.row.col.f32.f16.f16.f32 "
        "{%0,%1,%2,%3}, {%4,%5,%6,%7}, {%8,%9}, {%0,%1,%2,%3};"
        : "+f"(c[0]), "+f"(c[1]), "+f"(c[2]), "+f"(c[3])
        : "r"(a[0]), "r"(a[1]), "r"(a[2]), "r"(a[3]), "r"(b[0]), "r"(b[1]));
}

__device__ __forceinline__ void ldm_x4(uint32_t* r, const void* p) {
    uint32_t saddr = (uint32_t)__cvta_generic_to_shared(p);
    asm volatile(
        "ldmatrix.sync.aligned.m8n8.x4.shared.b16 {%0,%1,%2,%3}, [%4];"
        : "=r"(r[0]), "=r"(r[1]), "=r"(r[2]), "=r"(r[3]) : "r"(saddr));
}

__device__ __forceinline__ void cp16(void* smem_dst, const void* gsrc) {
    uint32_t d = (uint32_t)__cvta_generic_to_shared(smem_dst);
    asm volatile("cp.async.cg.shared.global [%0], [%1], 16;" :: "r"(d), "l"(gsrc));
}
#define CP_COMMIT() asm volatile("cp.async.commit_group;")
#define CP_WAIT(n)  asm volatile("cp.async.wait_group %0;" :: "n"(n))

// ---------------------------------------------------------------------------
__global__ void precompute_kernel() {
    int t = threadIdx.x;
    if (t < 32)
        g_invf[t] = (float)(1.0 / pow(10000.0, (double)t / 32.0));
}

// W [K][Nw] row-major -> Wt [Nw][K] row-major, fp16.
__global__ void transpose_h_kernel(const float* __restrict__ src,
                                   __half* __restrict__ dst, int K, int Nw) {
    __shared__ float t[32][33];
    int n0 = blockIdx.x * 32, k0 = blockIdx.y * 32;
    int x = threadIdx.x, y = threadIdx.y;      // 32 x 8
    #pragma unroll
    for (int i = 0; i < 32; i += 8)
        t[y + i][x] = src[(size_t)(k0 + y + i) * Nw + n0 + x];
    __syncthreads();
    #pragma unroll
    for (int i = 0; i < 32; i += 8)
        dst[(size_t)(n0 + y + i) * K + k0 + x] = __float2half_rn(t[x][y + i]);
}

// ---------------------------------------------------------------------------
__global__ void rmsnorm_kernel(const float* __restrict__ seq,
                               const float* __restrict__ wn) {
    int row = blockIdx.x;
    int t = threadIdx.x;
    const float4* in = reinterpret_cast<const float4*>(seq + (size_t)row * D_);
    float4 x = in[t];
    float ss = x.x * x.x + x.y * x.y + x.z * x.z + x.w * x.w;
    #pragma unroll
    for (int o = 16; o; o >>= 1) ss += __shfl_xor_sync(0xffffffffu, ss, o);
    __shared__ float red[8];
    if ((t & 31) == 0) red[t >> 5] = ss;
    __syncthreads();
    float tot = 0.f;
    #pragma unroll
    for (int iw = 0; iw < 8; iw++) tot += red[iw];
    float r = rsqrtf(tot * (1.0f / 1024.0f) + EPS_);
    float4 wv = reinterpret_cast<const float4*>(wn)[t];
    __half2* dst = reinterpret_cast<__half2*>(g_xnh + (size_t)row * D_);
    dst[2 * t]     = __floats2half2_rn(x.x * r * wv.x, x.y * r * wv.y);
    dst[2 * t + 1] = __floats2half2_rn(x.z * r * wv.z, x.w * r * wv.w);
}

// ---------------------------------------------------------------------------
// FP16 GEMM: C[M,N] = A[M,K] @ Bt[N,K]^T (fp16 in, fp32 accum/out).
// 128x128 tile, K-chunks of 32 halves, 4-stage cp.async ring, 256 threads,
// warp tile 32x64 via mma.sync.m16n8k16. Smem rows padded to 40 halves.
#define HLD   40
#define HSTG  4
#define HSSZ  (256 * HLD)              // halves per stage (A 128 + B 128 rows)
#define HSMEM_BYTES (HSTG * HSSZ * 2)  // 81920

__global__ __launch_bounds__(256, 2)
void h16_gemm_kernel(const __half* __restrict__ A, const __half* __restrict__ Bt,
                     float* __restrict__ C, int M, int N, int K) {
    extern __shared__ __half hs[];

    int tid  = threadIdx.x;
    int warp = tid >> 5;
    int lane = tid & 31;
    int wm = warp >> 1;          // 0..3 (M)
    int wn = warp & 1;           // 0..1 (N)
    int g   = lane >> 2;
    int tig = lane & 3;
    int lrow = lane & 15;
    int lseg = (lane >> 4) * 8;  // halves

    const __half* Ab  = A  + (size_t)(blockIdx.y * 128) * K;
    const __half* Bb  = Bt + (size_t)(blockIdx.x * 128) * K;
    const __half* grow = (tid < 128) ? (Ab + (size_t)tid * K)
                                     : (Bb + (size_t)(tid - 128) * K);

    float acc[2][8][4];
    #pragma unroll
    for (int a = 0; a < 2; a++)
        #pragma unroll
        for (int b = 0; b < 8; b++)
            #pragma unroll
            for (int c = 0; c < 4; c++) acc[a][b][c] = 0.f;

    int NK = K >> 5;   // chunks of 32 halves

    #pragma unroll
    for (int s = 0; s < HSTG - 1; s++) {
        __half* dst = hs + s * HSSZ + tid * HLD;
        #pragma unroll
        for (int i = 0; i < 4; i++)
            cp16(dst + i * 8, grow + s * 32 + i * 8);
        CP_COMMIT();
    }

    for (int kt = 0; kt < NK; kt++) {
        CP_WAIT(HSTG - 2);
        __syncthreads();

        int kn = kt + HSTG - 1;
        if (kn < NK) {
            __half* dst = hs + (kn & (HSTG - 1)) * HSSZ + tid * HLD;
            #pragma unroll
            for (int i = 0; i < 4; i++)
                cp16(dst + i * 8, grow + kn * 32 + i * 8);
        }
        CP_COMMIT();

        const __half* sA = hs + (kt & (HSTG - 1)) * HSSZ;
        const __half* sB = sA + 128 * HLD;

        #pragma unroll
        for (int ks = 0; ks < 2; ks++) {
            uint32_t afr[2][4];
            #pragma unroll
            for (int tm = 0; tm < 2; tm++)
                ldm_x4(afr[tm], sA + (wm * 32 + tm * 16 + lrow) * HLD + ks * 16 + lseg);
            uint32_t bfr[4][4];
            #pragma unroll
            for (int bj = 0; bj < 4; bj++)
                ldm_x4(bfr[bj], sB + (wn * 64 + bj * 16 + lrow) * HLD + ks * 16 + lseg);
            #pragma unroll
            for (int tm = 0; tm < 2; tm++)
                #pragma unroll
                for (int j = 0; j < 8; j++) {
                    uint32_t b[2] = { bfr[j >> 1][j & 1], bfr[j >> 1][2 + (j & 1)] };
                    mma_f16(acc[tm][j], afr[tm], b);
                }
        }
    }

    int rbase = blockIdx.y * 128 + wm * 32;
    int cbase = blockIdx.x * 128 + wn * 64;
    #pragma unroll
    for (int tm = 0; tm < 2; tm++) {
        #pragma unroll
        for (int j = 0; j < 8; j++) {
            int row0 = rbase + tm * 16 + g;
            int col  = cbase + j * 8 + 2 * tig;
            *reinterpret_cast<float2*>(&C[(size_t)row0 * N + col]) =
                make_float2(acc[tm][j][0], acc[tm][j][1]);
            *reinterpret_cast<float2*>(&C[(size_t)(row0 + 8) * N + col]) =
                make_float2(acc[tm][j][2], acc[tm][j][3]);
        }
    }
}

// ---------------------------------------------------------------------------
__global__ void rope_split_kernel() {
    int idx = blockIdx.x * blockDim.x + threadIdx.x;
    if (idx >= ROWS_ * H_ * 32) return;
    int t   = idx & 31;
    int h   = (idx >> 5) & 15;
    int row = idx >> 9;
    int n   = row & (N_ - 1);
    int b   = row >> 13;
    int w   = n >> 9;
    int s   = n & (SEG_ - 1);
    int seg = b * NW_ + w;

    const float* base = g_qkv + (size_t)row * 3072 + h * 64 + 2 * t;
    float q0 = base[0],    q1 = base[1];
    float k0 = base[1024], k1 = base[1025];
    float v0 = base[2048], v1 = base[2049];

    float ang = (float)n * g_invf[t];
    double ad = (double)ang;
    double kq = trunc(ad * 0.15915494309189535);
    ad -= kq * 6.283185307179586;
    float sn, cs;
    sincosf((float)ad, &sn, &cs);

    float qo0 = q0 * cs - q1 * sn;
    float qo1 = q1 * cs + q0 * sn;
    float ko0 = k0 * cs - k1 * sn;
    float ko1 = k1 * cs + k0 * sn;

    size_t dst = (((size_t)seg * H_ + h) * SEG_ + s) * DH_ + 2 * t;
    const float SC = 0.125f;
    g_q[dst] = tf32r(qo0 * SC); g_q[dst + 1] = tf32r(qo1 * SC);
    g_k[dst] = tf32r(ko0);      g_k[dst + 1] = tf32r(ko1);
    g_v[dst] = tf32r(v0);       g_v[dst + 1] = tf32r(v1);
}

// ---------------------------------------------------------------------------
// Tensor-core flash attention (tf32 mma; epilogue now emits fp16).
#define KP_ 72
#define PP_ 40

template<int NJ, bool PM>
__device__ __forceinline__ void attn_step(
    const float (*S)[KP_], float (*Psw)[PP_],
    const uint32_t qf[8][4], float o[8][4],
    float& m0, float& m1, float& l0, float& l1,
    int kv0, int i0, int i1, int g, int tig)
{
    float s[NJ][4];
    #pragma unroll
    for (int j = 0; j < NJ; j++)
        s[j][0] = s[j][1] = s[j][2] = s[j][3] = 0.f;

    #pragma unroll
    for (int ks = 0; ks < 8; ks++) {
        uint32_t b[NJ][2];
        #pragma unroll
        for (int j = 0; j < NJ; j++) {
            b[j][0] = __float_as_uint(S[j * 8 + g][ks * 8 + tig]);
            b[j][1] = __float_as_uint(S[j * 8 + g][ks * 8 + tig + 4]);
        }
        #pragma unroll
        for (int j = 0; j < NJ; j++)
            mma_tf32(s[j], qf[ks], b[j]);
    }

    if (!PM) {
        #pragma unroll
        for (int j = 0; j < NJ; j++) {
            int c0 = kv0 + j * 8 + 2 * tig;
            if (c0     > i0) s[j][0] = -1e30f;
            if (c0 + 1 > i0) s[j][1] = -1e30f;
            if (c0     > i1) s[j][2] = -1e30f;
            if (c0 + 1 > i1) s[j][3] = -1e30f;
        }
    }

    float cm0 = -1e30f, cm1 = -1e30f;
    #pragma unroll
    for (int j = 0; j < NJ; j++) {
        cm0 = fmaxf(cm0, fmaxf(s[j][0], s[j][1]));
        cm1 = fmaxf(cm1, fmaxf(s[j][2], s[j][3]));
    }
    cm0 = fmaxf(cm0, __shfl_xor_sync(0xffffffffu, cm0, 1));
    cm0 = fmaxf(cm0, __shfl_xor_sync(0xffffffffu, cm0, 2));
    cm1 = fmaxf(cm1, __shfl_xor_sync(0xffffffffu, cm1, 1));
    cm1 = fmaxf(cm1, __shfl_xor_sync(0xffffffffu, cm1, 2));

    float m0n = fmaxf(m0, cm0), m1n = fmaxf(m1, cm1);
    float cr0 = __expf(m0 - m0n), cr1 = __expf(m1 - m1n);
    m0 = m0n; m1 = m1n;

    float ps0 = 0.f, ps1 = 0.f;
    #pragma unroll
    for (int j = 0; j < NJ; j++) {
        float p0 = __expf(s[j][0] - m0n);
        float p1 = __expf(s[j][1] - m0n);
        float p2 = __expf(s[j][2] - m1n);
        float p3 = __expf(s[j][3] - m1n);
        ps0 += p0 + p1;
        ps1 += p2 + p3;
        *reinterpret_cast<float2*>(&Psw[g][j * 8 + 2 * tig])     = make_float2(p0, p1);
        *reinterpret_cast<float2*>(&Psw[g + 8][j * 8 + 2 * tig]) = make_float2(p2, p3);
    }
    ps0 += __shfl_xor_sync(0xffffffffu, ps0, 1);
    ps0 += __shfl_xor_sync(0xffffffffu, ps0, 2);
    ps1 += __shfl_xor_sync(0xffffffffu, ps1, 1);
    ps1 += __shfl_xor_sync(0xffffffffu, ps1, 2);
    l0 = l0 * cr0 + ps0;
    l1 = l1 * cr1 + ps1;

    #pragma unroll
    for (int j = 0; j < 8; j++) {
        o[j][0] *= cr0; o[j][1] *= cr0;
        o[j][2] *= cr1; o[j][3] *= cr1;
    }

    __syncwarp();
    #pragma unroll
    for (int ks2 = 0; ks2 < NJ; ks2++) {
        uint32_t a[4];
        a[0] = __float_as_uint(Psw[g][ks2 * 8 + tig]);
        a[1] = __float_as_uint(Psw[g + 8][ks2 * 8 + tig]);
        a[2] = __float_as_uint(Psw[g][ks2 * 8 + tig + 4]);
        a[3] = __float_as_uint(Psw[g + 8][ks2 * 8 + tig + 4]);
        #pragma unroll
        for (int j = 0; j < 8; j++) {
            uint32_t b[2];
            b[0] = __float_as_uint(S[32 + ks2 * 8 + tig][j * 8 + g]);
            b[1] = __float_as_uint(S[32 + ks2 * 8 + tig + 4][j * 8 + g]);
            mma_tf32(o[j], a, b);
        }
    }
}

__global__ __launch_bounds__(128)
void attn_mma_kernel(const float* __restrict__ pm) {
    int qt  = blockIdx.x;
    int h   = blockIdx.y;
    int seg = blockIdx.z;
    int tid = threadIdx.x;
    int w    = tid >> 5;
    int lane = tid & 31;
    int g   = lane >> 2;
    int tig = lane & 3;

    __shared__ float S[64][KP_];
    __shared__ float Ps[4][16][PP_];

    const float* qbase = g_q + (((size_t)seg * H_ + h) * SEG_ + qt * 64) * DH_;
    #pragma unroll
    for (int i = 0; i < 8; i++) {
        int idx = tid + i * 128;
        int r = idx >> 4, c = idx & 15;
        *reinterpret_cast<float4*>(&S[r][c * 4]) =
            *reinterpret_cast<const float4*>(qbase + (size_t)r * DH_ + c * 4);
    }
    __syncthreads();

    uint32_t qf[8][4];
    #pragma unroll
    for (int ks = 0; ks < 8; ks++) {
        qf[ks][0] = __float_as_uint(S[w * 16 + g][ks * 8 + tig]);
        qf[ks][1] = __float_as_uint(S[w * 16 + g + 8][ks * 8 + tig]);
        qf[ks][2] = __float_as_uint(S[w * 16 + g][ks * 8 + tig + 4]);
        qf[ks][3] = __float_as_uint(S[w * 16 + g + 8][ks * 8 + tig + 4]);
    }

    float o[8][4];
    #pragma unroll
    for (int j = 0; j < 8; j++)
        o[j][0] = o[j][1] = o[j][2] = o[j][3] = 0.f;
    float m0 = -1e30f, m1 = -1e30f, l0 = 0.f, l1 = 0.f;

    int i0 = qt * 64 + w * 16 + g;
    int i1 = i0 + 8;

    const float* kb  = g_k + (((size_t)seg * H_ + h) * SEG_) * DH_;
    const float* vb  = g_v + (((size_t)seg * H_ + h) * SEG_) * DH_;
    const float* pmk = pm + (size_t)h * P_ * DH_;
    const float* pmv = pm + (size_t)(H_ + h) * P_ * DH_;

    int nseg = 2 * qt + 2;

    for (int ch = 0; ch <= nseg; ch++) {
        __syncthreads();
        if (ch == 0) {
            #pragma unroll
            for (int i = 0; i < 2; i++) {
                int idx = tid + i * 128;
                int r = idx >> 4, c = idx & 15;
                *reinterpret_cast<float4*>(&S[r][c * 4]) =
                    *reinterpret_cast<const float4*>(pmk + (size_t)r * DH_ + c * 4);
                *reinterpret_cast<float4*>(&S[32 + r][c * 4]) =
                    *reinterpret_cast<const float4*>(pmv + (size_t)r * DH_ + c * 4);
            }
        } else {
            int kv0 = (ch - 1) * 32;
            #pragma unroll
            for (int i = 0; i < 4; i++) {
                int idx = tid + i * 128;
                int r = idx >> 4, c = idx & 15;
                *reinterpret_cast<float4*>(&S[r][c * 4]) =
                    *reinterpret_cast<const float4*>(kb + (size_t)(kv0 + r) * DH_ + c * 4);
                *reinterpret_cast<float4*>(&S[32 + r][c * 4]) =
                    *reinterpret_cast<const float4*>(vb + (size_t)(kv0 + r) * DH_ + c * 4);
            }
        }
        __syncthreads();

        if (ch == 0)
            attn_step<2, true>(S, Ps[w], qf, o, m0, m1, l0, l1, 0, i0, i1, g, tig);
        else
            attn_step<4, false>(S, Ps[w], qf, o, m0, m1, l0, l1, (ch - 1) * 32, i0, i1, g, tig);
    }

    float inv0 = 1.f / l0, inv1 = 1.f / l1;
    size_t r0 = (size_t)(seg * SEG_ + i0) * D_ + h * DH_;
    size_t r1 = (size_t)(seg * SEG_ + i1) * D_ + h * DH_;
    #pragma unroll
    for (int j = 0; j < 8; j++) {
        int col = j * 8 + 2 * tig;
        *reinterpret_cast<__half2*>(&g_aoh[r0 + col]) =
            __floats2half2_rn(o[j][0] * inv0, o[j][1] * inv0);
        *reinterpret_cast<__half2*>(&g_aoh[r1 + col]) =
            __floats2half2_rn(o[j][2] * inv1, o[j][3] * inv1);
    }
}

// ---------------------------------------------------------------------------
extern "C" void kernel_launch(void* const* d_in, const int* in_sizes, int n_in,
                              void* d_out, int out_size) {
    const float* seq    = (const float*)d_in[0];
    const float* w_norm = (const float*)d_in[1];
    const float* Wqkv   = (const float*)d_in[2];
    const float* Wout   = (const float*)d_in[3];
    const float* pm     = (const float*)d_in[4];
    float* out = (float*)d_out;

    __half* xnh = nullptr; cudaGetSymbolAddress((void**)&xnh, g_xnh);
    float*  qkv = nullptr; cudaGetSymbolAddress((void**)&qkv, g_qkv);
    __half* aoh = nullptr; cudaGetSymbolAddress((void**)&aoh, g_aoh);
    __half* wqh = nullptr; cudaGetSymbolAddress((void**)&wqh, g_wqh);
    __half* woh = nullptr; cudaGetSymbolAddress((void**)&woh, g_woh);

    cudaFuncSetAttribute(h16_gemm_kernel,
                         cudaFuncAttributeMaxDynamicSharedMemorySize, HSMEM_BYTES);

    precompute_kernel<<<1, 32>>>();
    {
        dim3 blk(32, 8);
        dim3 grq(3072 / 32, 1024 / 32);
        transpose_h_kernel<<<grq, blk>>>(Wqkv, wqh, 1024, 3072);
        dim3 gro(1024 / 32, 1024 / 32);
        transpose_h_kernel<<<gro, blk>>>(Wout, woh, 1024, 1024);
    }
    rmsnorm_kernel<<<ROWS_, 256>>>(seq, w_norm);
    {
        dim3 grid(3072 / 128, ROWS_ / 128);
        h16_gemm_kernel<<<grid, 256, HSMEM_BYTES>>>(xnh, wqh, qkv, ROWS_, 3072, 1024);
    }
    {
        int total = ROWS_ * H_ * 32;
        rope_split_kernel<<<(total + 255) / 256, 256>>>();
    }
    {
        dim3 grid(8, H_, 32);
        attn_mma_kernel<<<grid, 128>>>(pm);
    }
    {
        dim3 grid(1024 / 128, ROWS_ / 128);
        h16_gemm_kernel<<<grid, 256, HSMEM_BYTES>>>(aoh, woh, out, ROWS_, 1024, 1024);
    }
}

// round 8
// speedup vs baseline: 1.2751x; 1.0502x over previous
#include <cuda_runtime.h>
#include <cuda_fp16.h>
#include <math.h>
#include <stdint.h>

// ---------------------------------------------------------------------------
// Round 8: RoPE fused into GEMM1 epilogue via precomputed cos/sin table.
// qkv intermediate + rope kernel eliminated. fp16 mma GEMMs, tf32 attention.
// ---------------------------------------------------------------------------

#define B_   2
#define N_   8192
#define D_   1024
#define H_   16
#define DH_  64
#define SEG_ 512
#define P_   16
#define NW_  16
#define ROWS_ (B_ * N_)      // 16384
#define EPS_ 1.1920929e-07f

__device__ __half g_xnh [(size_t)ROWS_ * D_];        // rmsnorm out, fp16
__device__ float  g_q   [(size_t)32 * H_ * SEG_ * DH_];
__device__ float  g_k   [(size_t)32 * H_ * SEG_ * DH_];
__device__ float  g_v   [(size_t)32 * H_ * SEG_ * DH_];
__device__ __half g_aoh [(size_t)ROWS_ * D_];        // attention out, fp16
__device__ __half g_wqh [(size_t)D_ * 3 * D_];       // Wqkv^T [3072][1024] fp16
__device__ __half g_woh [(size_t)D_ * D_];           // Wout^T [1024][1024] fp16
__device__ float  g_invf[32];
__device__ float2 g_cs  [(size_t)N_ * 32];           // cos/sin table, 2 MB

__device__ __forceinline__ float tf32r(float x) {
    uint32_t u;
    asm("cvt.rna.tf32.f32 %0, %1;" : "=r"(u) : "f"(x));
    return __uint_as_float(u);
}

__device__ __forceinline__ void mma_tf32(float* c, const uint32_t* a, const uint32_t* b) {
    asm volatile(
        "mma.sync.aligned.m16n8k8.row.col.f32.tf32.tf32.f32 "
        "{%0,%1,%2,%3}, {%4,%5,%6,%7}, {%8,%9}, {%0,%1,%2,%3};"
        : "+f"(c[0]), "+f"(c[1]), "+f"(c[2]), "+f"(c[3])
        : "r"(a[0]), "r"(a[1]), "r"(a[2]), "r"(a[3]), "r"(b[0]), "r"(b[1]));
}

__device__ __forceinline__ void mma_f16(float* c, const uint32_t* a, const uint32_t* b) {
    asm volatile(
        "mma.sync.aligned.m16n8k16.row.col.f32.f16.f16.f32 "
        "{%0,%1,%2,%3}, {%4,%5,%6,%7}, {%8,%9}, {%0,%1,%2,%3};"
        : "+f"(c[0]), "+f"(c[1]), "+f"(c[2]), "+f"(c[3])
        : "r"(a[0]), "r"(a[1]), "r"(a[2]), "r"(a[3]), "r"(b[0]), "r"(b[1]));
}

__device__ __forceinline__ void ldm_x4(uint32_t* r, const void* p) {
    uint32_t saddr = (uint32_t)__cvta_generic_to_shared(p);
    asm volatile(
        "ldmatrix.sync.aligned.m8n8.x4.shared.b16 {%0,%1,%2,%3}, [%4];"
        : "=r"(r[0]), "=r"(r[1]), "=r"(r[2]), "=r"(r[3]) : "r"(saddr));
}

__device__ __forceinline__ void cp16(void* smem_dst, const void* gsrc) {
    uint32_t d = (uint32_t)__cvta_generic_to_shared(smem_dst);
    asm volatile("cp.async.cg.shared.global [%0], [%1], 16;" :: "r"(d), "l"(gsrc));
}
#define CP_COMMIT() asm volatile("cp.async.commit_group;")
#define CP_WAIT(n)  asm volatile("cp.async.wait_group %0;" :: "n"(n))

// ---------------------------------------------------------------------------
__global__ void precompute_kernel() {
    int t = threadIdx.x;
    if (t < 32)
        g_invf[t] = (float)(1.0 / pow(10000.0, (double)t / 32.0));
}

// cos/sin table: g_cs[n*32+t] for n in [0,8192), t in [0,32)
__global__ void rope_table_kernel() {
    int idx = blockIdx.x * blockDim.x + threadIdx.x;
    if (idx >= N_ * 32) return;
    int t = idx & 31;
    int n = idx >> 5;
    float ang = (float)n * g_invf[t];
    double ad = (double)ang;
    double kq = trunc(ad * 0.15915494309189535);
    ad -= kq * 6.283185307179586;
    float sn, cs;
    sincosf((float)ad, &sn, &cs);
    g_cs[idx] = make_float2(cs, sn);
}

// W [K][Nw] row-major -> Wt [Nw][K] row-major, fp16.
__global__ void transpose_h_kernel(const float* __restrict__ src,
                                   __half* __restrict__ dst, int K, int Nw) {
    __shared__ float t[32][33];
    int n0 = blockIdx.x * 32, k0 = blockIdx.y * 32;
    int x = threadIdx.x, y = threadIdx.y;      // 32 x 8
    #pragma unroll
    for (int i = 0; i < 32; i += 8)
        t[y + i][x] = src[(size_t)(k0 + y + i) * Nw + n0 + x];
    __syncthreads();
    #pragma unroll
    for (int i = 0; i < 32; i += 8)
        dst[(size_t)(n0 + y + i) * K + k0 + x] = __float2half_rn(t[x][y + i]);
}

// ---------------------------------------------------------------------------
__global__ void rmsnorm_kernel(const float* __restrict__ seq,
                               const float* __restrict__ wn) {
    int row = blockIdx.x;
    int t = threadIdx.x;
    const float4* in = reinterpret_cast<const float4*>(seq + (size_t)row * D_);
    float4 x = in[t];
    float ss = x.x * x.x + x.y * x.y + x.z * x.z + x.w * x.w;
    #pragma unroll
    for (int o = 16; o; o >>= 1) ss += __shfl_xor_sync(0xffffffffu, ss, o);
    __shared__ float red[8];
    if ((t & 31) == 0) red[t >> 5] = ss;
    __syncthreads();
    float tot = 0.f;
    #pragma unroll
    for (int iw = 0; iw < 8; iw++) tot += red[iw];
    float r = rsqrtf(tot * (1.0f / 1024.0f) + EPS_);
    float4 wv = reinterpret_cast<const float4*>(wn)[t];
    __half2* dst = reinterpret_cast<__half2*>(g_xnh + (size_t)row * D_);
    dst[2 * t]     = __floats2half2_rn(x.x * r * wv.x, x.y * r * wv.y);
    dst[2 * t + 1] = __floats2half2_rn(x.z * r * wv.z, x.w * r * wv.w);
}

// ---------------------------------------------------------------------------
// FP16 GEMM: C[M,N] = A[M,K] @ Bt[N,K]^T (fp16 in, fp32 accum).
// FUSE=0: plain fp32 C store. FUSE=1: RoPE+scatter epilogue into g_q/g_k/g_v.
#define HLD   40
#define HSTG  4
#define HSSZ  (256 * HLD)
#define HSMEM_BYTES (HSTG * HSSZ * 2)  // 81920

template<int FUSE>
__global__ __launch_bounds__(256, 2)
void h16_gemm_kernel(const __half* __restrict__ A, const __half* __restrict__ Bt,
                     float* __restrict__ C, int M, int N, int K) {
    extern __shared__ __half hs[];

    int tid  = threadIdx.x;
    int warp = tid >> 5;
    int lane = tid & 31;
    int wm = warp >> 1;
    int wn = warp & 1;
    int g   = lane >> 2;
    int tig = lane & 3;
    int lrow = lane & 15;
    int lseg = (lane >> 4) * 8;

    const __half* Ab  = A  + (size_t)(blockIdx.y * 128) * K;
    const __half* Bb  = Bt + (size_t)(blockIdx.x * 128) * K;
    const __half* grow = (tid < 128) ? (Ab + (size_t)tid * K)
                                     : (Bb + (size_t)(tid - 128) * K);

    float acc[2][8][4];
    #pragma unroll
    for (int a = 0; a < 2; a++)
        #pragma unroll
        for (int b = 0; b < 8; b++)
            #pragma unroll
            for (int c = 0; c < 4; c++) acc[a][b][c] = 0.f;

    int NK = K >> 5;

    #pragma unroll
    for (int s = 0; s < HSTG - 1; s++) {
        __half* dst = hs + s * HSSZ + tid * HLD;
        #pragma unroll
        for (int i = 0; i < 4; i++)
            cp16(dst + i * 8, grow + s * 32 + i * 8);
        CP_COMMIT();
    }

    for (int kt = 0; kt < NK; kt++) {
        CP_WAIT(HSTG - 2);
        __syncthreads();

        int kn = kt + HSTG - 1;
        if (kn < NK) {
            __half* dst = hs + (kn & (HSTG - 1)) * HSSZ + tid * HLD;
            #pragma unroll
            for (int i = 0; i < 4; i++)
                cp16(dst + i * 8, grow + kn * 32 + i * 8);
        }
        CP_COMMIT();

        const __half* sA = hs + (kt & (HSTG - 1)) * HSSZ;
        const __half* sB = sA + 128 * HLD;

        #pragma unroll
        for (int ks = 0; ks < 2; ks++) {
            uint32_t afr[2][4];
            #pragma unroll
            for (int tm = 0; tm < 2; tm++)
                ldm_x4(afr[tm], sA + (wm * 32 + tm * 16 + lrow) * HLD + ks * 16 + lseg);
            uint32_t bfr[4][4];
            #pragma unroll
            for (int bj = 0; bj < 4; bj++)
                ldm_x4(bfr[bj], sB + (wn * 64 + bj * 16 + lrow) * HLD + ks * 16 + lseg);
            #pragma unroll
            for (int tm = 0; tm < 2; tm++)
                #pragma unroll
                for (int j = 0; j < 8; j++) {
                    uint32_t b[2] = { bfr[j >> 1][j & 1], bfr[j >> 1][2 + (j & 1)] };
                    mma_f16(acc[tm][j], afr[tm], b);
                }
        }
    }

    int rbase = blockIdx.y * 128 + wm * 32;
    int cbase = blockIdx.x * 128 + wn * 64;

    if (FUSE == 0) {
        #pragma unroll
        for (int tm = 0; tm < 2; tm++) {
            #pragma unroll
            for (int j = 0; j < 8; j++) {
                int row0 = rbase + tm * 16 + g;
                int col  = cbase + j * 8 + 2 * tig;
                *reinterpret_cast<float2*>(&C[(size_t)row0 * N + col]) =
                    make_float2(acc[tm][j][0], acc[tm][j][1]);
                *reinterpret_cast<float2*>(&C[(size_t)(row0 + 8) * N + col]) =
                    make_float2(acc[tm][j][2], acc[tm][j][3]);
            }
        }
    } else {
        // RoPE + scatter epilogue. Section (q/k/v) is uniform per CTA.
        int sect = (cbase >> 10);          // 0=q, 1=k, 2=v
        #pragma unroll
        for (int tm = 0; tm < 2; tm++) {
            #pragma unroll
            for (int rr = 0; rr < 2; rr++) {
                int row = rbase + tm * 16 + g + rr * 8;
                int n   = row & (N_ - 1);
                int seg = (row >> 13) * NW_ + (n >> 9);
                int s   = n & (SEG_ - 1);
                size_t base = (((size_t)seg * H_) * SEG_ + s) * DH_;
                #pragma unroll
                for (int j = 0; j < 8; j++) {
                    float x0 = acc[tm][j][rr * 2 + 0];
                    float x1 = acc[tm][j][rr * 2 + 1];
                    int cq = (cbase & 1023) + j * 8 + 2 * tig;
                    int h = cq >> 6, d = cq & 63;
                    size_t dst = base + (size_t)h * (SEG_ * DH_) + d;
                    if (sect == 2) {
                        *reinterpret_cast<float2*>(&g_v[dst]) =
                            make_float2(tf32r(x0), tf32r(x1));
                    } else {
                        float2 cssn = g_cs[(size_t)n * 32 + (d >> 1)];
                        float y0 = x0 * cssn.x - x1 * cssn.y;
                        float y1 = x1 * cssn.x + x0 * cssn.y;
                        if (sect == 0) {
                            *reinterpret_cast<float2*>(&g_q[dst]) =
                                make_float2(tf32r(y0 * 0.125f), tf32r(y1 * 0.125f));
                        } else {
                            *reinterpret_cast<float2*>(&g_k[dst]) =
                                make_float2(tf32r(y0), tf32r(y1));
                        }
                    }
                }
            }
        }
    }
}

// ---------------------------------------------------------------------------
// Tensor-core flash attention (tf32 mma; epilogue emits fp16).
#define KP_ 72
#define PP_ 40

template<int NJ, bool PM>
__device__ __forceinline__ void attn_step(
    const float (*S)[KP_], float (*Psw)[PP_],
    const uint32_t qf[8][4], float o[8][4],
    float& m0, float& m1, float& l0, float& l1,
    int kv0, int i0, int i1, int g, int tig)
{
    float s[NJ][4];
    #pragma unroll
    for (int j = 0; j < NJ; j++)
        s[j][0] = s[j][1] = s[j][2] = s[j][3] = 0.f;

    #pragma unroll
    for (int ks = 0; ks < 8; ks++) {
        uint32_t b[NJ][2];
        #pragma unroll
        for (int j = 0; j < NJ; j++) {
            b[j][0] = __float_as_uint(S[j * 8 + g][ks * 8 + tig]);
            b[j][1] = __float_as_uint(S[j * 8 + g][ks * 8 + tig + 4]);
        }
        #pragma unroll
        for (int j = 0; j < NJ; j++)
            mma_tf32(s[j], qf[ks], b[j]);
    }

    if (!PM) {
        #pragma unroll
        for (int j = 0; j < NJ; j++) {
            int c0 = kv0 + j * 8 + 2 * tig;
            if (c0     > i0) s[j][0] = -1e30f;
            if (c0 + 1 > i0) s[j][1] = -1e30f;
            if (c0     > i1) s[j][2] = -1e30f;
            if (c0 + 1 > i1) s[j][3] = -1e30f;
        }
    }

    float cm0 = -1e30f, cm1 = -1e30f;
    #pragma unroll
    for (int j = 0; j < NJ; j++) {
        cm0 = fmaxf(cm0, fmaxf(s[j][0], s[j][1]));
        cm1 = fmaxf(cm1, fmaxf(s[j][2], s[j][3]));
    }
    cm0 = fmaxf(cm0, __shfl_xor_sync(0xffffffffu, cm0, 1));
    cm0 = fmaxf(cm0, __shfl_xor_sync(0xffffffffu, cm0, 2));
    cm1 = fmaxf(cm1, __shfl_xor_sync(0xffffffffu, cm1, 1));
    cm1 = fmaxf(cm1, __shfl_xor_sync(0xffffffffu, cm1, 2));

    float m0n = fmaxf(m0, cm0), m1n = fmaxf(m1, cm1);
    float cr0 = __expf(m0 - m0n), cr1 = __expf(m1 - m1n);
    m0 = m0n; m1 = m1n;

    float ps0 = 0.f, ps1 = 0.f;
    #pragma unroll
    for (int j = 0; j < NJ; j++) {
        float p0 = __expf(s[j][0] - m0n);
        float p1 = __expf(s[j][1] - m0n);
        float p2 = __expf(s[j][2] - m1n);
        float p3 = __expf(s[j][3] - m1n);
        ps0 += p0 + p1;
        ps1 += p2 + p3;
        *reinterpret_cast<float2*>(&Psw[g][j * 8 + 2 * tig])     = make_float2(p0, p1);
        *reinterpret_cast<float2*>(&Psw[g + 8][j * 8 + 2 * tig]) = make_float2(p2, p3);
    }
    ps0 += __shfl_xor_sync(0xffffffffu, ps0, 1);
    ps0 += __shfl_xor_sync(0xffffffffu, ps0, 2);
    ps1 += __shfl_xor_sync(0xffffffffu, ps1, 1);
    ps1 += __shfl_xor_sync(0xffffffffu, ps1, 2);
    l0 = l0 * cr0 + ps0;
    l1 = l1 * cr1 + ps1;

    #pragma unroll
    for (int j = 0; j < 8; j++) {
        o[j][0] *= cr0; o[j][1] *= cr0;
        o[j][2] *= cr1; o[j][3] *= cr1;
    }

    __syncwarp();
    #pragma unroll
    for (int ks2 = 0; ks2 < NJ; ks2++) {
        uint32_t a[4];
        a[0] = __float_as_uint(Psw[g][ks2 * 8 + tig]);
        a[1] = __float_as_uint(Psw[g + 8][ks2 * 8 + tig]);
        a[2] = __float_as_uint(Psw[g][ks2 * 8 + tig + 4]);
        a[3] = __float_as_uint(Psw[g + 8][ks2 * 8 + tig + 4]);
        #pragma unroll
        for (int j = 0; j < 8; j++) {
            uint32_t b[2];
            b[0] = __float_as_uint(S[32 + ks2 * 8 + tig][j * 8 + g]);
            b[1] = __float_as_uint(S[32 + ks2 * 8 + tig + 4][j * 8 + g]);
            mma_tf32(o[j], a, b);
        }
    }
}

__global__ __launch_bounds__(128)
void attn_mma_kernel(const float* __restrict__ pm) {
    int qt  = blockIdx.x;
    int h   = blockIdx.y;
    int seg = blockIdx.z;
    int tid = threadIdx.x;
    int w    = tid >> 5;
    int lane = tid & 31;
    int g   = lane >> 2;
    int tig = lane & 3;

    __shared__ float S[64][KP_];
    __shared__ float Ps[4][16][PP_];

    const float* qbase = g_q + (((size_t)seg * H_ + h) * SEG_ + qt * 64) * DH_;
    #pragma unroll
    for (int i = 0; i < 8; i++) {
        int idx = tid + i * 128;
        int r = idx >> 4, c = idx & 15;
        *reinterpret_cast<float4*>(&S[r][c * 4]) =
            *reinterpret_cast<const float4*>(qbase + (size_t)r * DH_ + c * 4);
    }
    __syncthreads();

    uint32_t qf[8][4];
    #pragma unroll
    for (int ks = 0; ks < 8; ks++) {
        qf[ks][0] = __float_as_uint(S[w * 16 + g][ks * 8 + tig]);
        qf[ks][1] = __float_as_uint(S[w * 16 + g + 8][ks * 8 + tig]);
        qf[ks][2] = __float_as_uint(S[w * 16 + g][ks * 8 + tig + 4]);
        qf[ks][3] = __float_as_uint(S[w * 16 + g + 8][ks * 8 + tig + 4]);
    }

    float o[8][4];
    #pragma unroll
    for (int j = 0; j < 8; j++)
        o[j][0] = o[j][1] = o[j][2] = o[j][3] = 0.f;
    float m0 = -1e30f, m1 = -1e30f, l0 = 0.f, l1 = 0.f;

    int i0 = qt * 64 + w * 16 + g;
    int i1 = i0 + 8;

    const float* kb  = g_k + (((size_t)seg * H_ + h) * SEG_) * DH_;
    const float* vb  = g_v + (((size_t)seg * H_ + h) * SEG_) * DH_;
    const float* pmk = pm + (size_t)h * P_ * DH_;
    const float* pmv = pm + (size_t)(H_ + h) * P_ * DH_;

    int nseg = 2 * qt + 2;

    for (int ch = 0; ch <= nseg; ch++) {
        __syncthreads();
        if (ch == 0) {
            #pragma unroll
            for (int i = 0; i < 2; i++) {
                int idx = tid + i * 128;
                int r = idx >> 4, c = idx & 15;
                *reinterpret_cast<float4*>(&S[r][c * 4]) =
                    *reinterpret_cast<const float4*>(pmk + (size_t)r * DH_ + c * 4);
                *reinterpret_cast<float4*>(&S[32 + r][c * 4]) =
                    *reinterpret_cast<const float4*>(pmv + (size_t)r * DH_ + c * 4);
            }
        } else {
            int kv0 = (ch - 1) * 32;
            #pragma unroll
            for (int i = 0; i < 4; i++) {
                int idx = tid + i * 128;
                int r = idx >> 4, c = idx & 15;
                *reinterpret_cast<float4*>(&S[r][c * 4]) =
                    *reinterpret_cast<const float4*>(kb + (size_t)(kv0 + r) * DH_ + c * 4);
                *reinterpret_cast<float4*>(&S[32 + r][c * 4]) =
                    *reinterpret_cast<const float4*>(vb + (size_t)(kv0 + r) * DH_ + c * 4);
            }
        }
        __syncthreads();

        if (ch == 0)
            attn_step<2, true>(S, Ps[w], qf, o, m0, m1, l0, l1, 0, i0, i1, g, tig);
        else
            attn_step<4, false>(S, Ps[w], qf, o, m0, m1, l0, l1, (ch - 1) * 32, i0, i1, g, tig);
    }

    float inv0 = 1.f / l0, inv1 = 1.f / l1;
    size_t r0 = (size_t)(seg * SEG_ + i0) * D_ + h * DH_;
    size_t r1 = (size_t)(seg * SEG_ + i1) * D_ + h * DH_;
    #pragma unroll
    for (int j = 0; j < 8; j++) {
        int col = j * 8 + 2 * tig;
        *reinterpret_cast<__half2*>(&g_aoh[r0 + col]) =
            __floats2half2_rn(o[j][0] * inv0, o[j][1] * inv0);
        *reinterpret_cast<__half2*>(&g_aoh[r1 + col]) =
            __floats2half2_rn(o[j][2] * inv1, o[j][3] * inv1);
    }
}

// ---------------------------------------------------------------------------
extern "C" void kernel_launch(void* const* d_in, const int* in_sizes, int n_in,
                              void* d_out, int out_size) {
    const float* seq    = (const float*)d_in[0];
    const float* w_norm = (const float*)d_in[1];
    const float* Wqkv   = (const float*)d_in[2];
    const float* Wout   = (const float*)d_in[3];
    const float* pm     = (const float*)d_in[4];
    float* out = (float*)d_out;

    __half* xnh = nullptr; cudaGetSymbolAddress((void**)&xnh, g_xnh);
    __half* aoh = nullptr; cudaGetSymbolAddress((void**)&aoh, g_aoh);
    __half* wqh = nullptr; cudaGetSymbolAddress((void**)&wqh, g_wqh);
    __half* woh = nullptr; cudaGetSymbolAddress((void**)&woh, g_woh);

    cudaFuncSetAttribute(h16_gemm_kernel<0>,
                         cudaFuncAttributeMaxDynamicSharedMemorySize, HSMEM_BYTES);
    cudaFuncSetAttribute(h16_gemm_kernel<1>,
                         cudaFuncAttributeMaxDynamicSharedMemorySize, HSMEM_BYTES);

    precompute_kernel<<<1, 32>>>();
    rope_table_kernel<<<(N_ * 32) / 256, 256>>>();
    {
        dim3 blk(32, 8);
        dim3 grq(3072 / 32, 1024 / 32);
        transpose_h_kernel<<<grq, blk>>>(Wqkv, wqh, 1024, 3072);
        dim3 gro(1024 / 32, 1024 / 32);
        transpose_h_kernel<<<gro, blk>>>(Wout, woh, 1024, 1024);
    }
    rmsnorm_kernel<<<ROWS_, 256>>>(seq, w_norm);
    {
        dim3 grid(3072 / 128, ROWS_ / 128);
        h16_gemm_kernel<1><<<grid, 256, HSMEM_BYTES>>>(xnh, wqh, nullptr, ROWS_, 3072, 1024);
    }
    {
        dim3 grid(8, H_, 32);
        attn_mma_kernel<<<grid, 128>>>(pm);
    }
    {
        dim3 grid(1024 / 128, ROWS_ / 128);
        h16_gemm_kernel<0><<<grid, 256, HSMEM_BYTES>>>(aoh, woh, out, ROWS_, 1024, 1024);
    }
}